// round 3
// baseline (speedup 1.0000x reference)
#include <cuda_runtime.h>

#define NN 50000
#define EE 800000
#define DD 128
#define RR 4
#define ND (NN*DD)

// ---------------- persistent scratch (device globals; no allocation) -------
__device__ float g_emb[RR][ND];          // per-relation node embeddings
__device__ float g_h[ND];                // GAT-transformed features
__device__ float g_out[ND];              // conv output (pre-BN)
__device__ float g_msg[ND];              // weighted message accumulator
__device__ float g_relv[RR*DD];          // relation vectors
__device__ float g_asrc[NN], g_adst[NN], g_emax[NN], g_denom[NN];
__device__ float g_edge_e[EE];
__device__ float g_colsum[DD], g_colsq[DD], g_mu[DD], g_istd[DD];

__device__ __forceinline__ void atomicMaxFloat(float* addr, float v) {
    // works for mixed-sign IEEE floats (int-max for >=0, uint-min for <0)
    if (v >= 0.f) atomicMax((int*)addr, __float_as_int(v));
    else          atomicMin((unsigned int*)addr, __float_as_uint(v));
}

// ---------------- init: emb[k] = features, relv = rel_emb ------------------
__global__ void k_init(const float* __restrict__ features,
                       const float* __restrict__ rel_emb) {
    int i = blockIdx.x * blockDim.x + threadIdx.x;
    if (i < ND) {
        float f = features[i];
#pragma unroll
        for (int k = 0; k < RR; k++) g_emb[k][i] = f;
    }
    if (i < RR * DD) g_relv[i] = rel_emb[i];
}

// ---------------- per-conv reset -------------------------------------------
__global__ void k_reset() {
    int i = blockIdx.x * blockDim.x + threadIdx.x;
    if (i < ND) g_msg[i] = 0.f;
    if (i < NN) { g_denom[i] = 0.f; g_emax[i] = __int_as_float(0xFF800000); }
    if (i < DD) { g_colsum[i] = 0.f; g_colsq[i] = 0.f; }
}

// ---------------- SGEMM: h = (emb[k] * relv[k]) @ W  (M=N rows, K=N=128) ---
// BM=64, BN=128(full), BK=32. 256 threads; thread tile 8 rows x 4 cols.
__global__ __launch_bounds__(256) void k_gemm(int k, const float* __restrict__ W) {
    __shared__ float  xs[64][32];
    __shared__ float4 ws[32][32];      // ws[kk][c4] = W[k0+kk][4*c4 .. +3]
    const float* __restrict__ X  = g_emb[k];
    const float* __restrict__ rv = g_relv + k * DD;

    int tid = threadIdx.x;
    int tx = tid & 31, ty = tid >> 5;
    int row0 = blockIdx.x * 64;

    float acc[8][4];
#pragma unroll
    for (int i = 0; i < 8; i++)
#pragma unroll
        for (int j = 0; j < 4; j++) acc[i][j] = 0.f;

    for (int k0 = 0; k0 < DD; k0 += 32) {
#pragma unroll
        for (int j = 0; j < 8; j++) {
            int idx = tid + j * 256;           // 2048 elems
            int r = idx >> 5, kk = idx & 31;
            int gr = row0 + r;
            xs[r][kk] = (gr < NN) ? X[(size_t)gr * DD + k0 + kk] * rv[k0 + kk] : 0.f;
        }
#pragma unroll
        for (int j = 0; j < 4; j++) {
            int idx = tid + j * 256;           // 1024 float4
            int kk = idx >> 5, c4 = idx & 31;
            ws[kk][c4] = reinterpret_cast<const float4*>(W + (size_t)(k0 + kk) * DD)[c4];
        }
        __syncthreads();
#pragma unroll
        for (int kk = 0; kk < 32; kk++) {
            float4 b4 = ws[kk][tx];
#pragma unroll
            for (int i = 0; i < 8; i++) {
                float a = xs[ty * 8 + i][kk];
                acc[i][0] += a * b4.x; acc[i][1] += a * b4.y;
                acc[i][2] += a * b4.z; acc[i][3] += a * b4.w;
            }
        }
        __syncthreads();
    }
#pragma unroll
    for (int i = 0; i < 8; i++) {
        int gr = row0 + ty * 8 + i;
        if (gr < NN) {
            float4 v = make_float4(acc[i][0], acc[i][1], acc[i][2], acc[i][3]);
            reinterpret_cast<float4*>(g_h + (size_t)gr * DD)[tx] = v;
        }
    }
}

// ---------------- alpha_src/adst per node (warp per row) -------------------
__global__ void k_alpha(const float* __restrict__ a_src,
                        const float* __restrict__ a_dst) {
    int warp = (blockIdx.x * blockDim.x + threadIdx.x) >> 5;
    int lane = threadIdx.x & 31;
    if (warp >= NN) return;
    const float* hr = g_h + (size_t)warp * DD;
    float s1 = 0.f, s2 = 0.f;
#pragma unroll
    for (int j = 0; j < 4; j++) {
        float v = hr[lane + 32 * j];
        s1 += v * a_src[lane + 32 * j];
        s2 += v * a_dst[lane + 32 * j];
    }
#pragma unroll
    for (int o = 16; o; o >>= 1) {
        s1 += __shfl_down_sync(0xffffffffu, s1, o);
        s2 += __shfl_down_sync(0xffffffffu, s2, o);
    }
    if (lane == 0) { g_asrc[warp] = s1; g_adst[warp] = s2; }
}

// ---------------- edge pass A: e + segment max -----------------------------
__global__ void k_edgeA(const int* __restrict__ src,
                        const int* __restrict__ dst) {
    int e = blockIdx.x * blockDim.x + threadIdx.x;
    if (e >= EE) return;
    int s = src[e], d = dst[e];
    float v = g_asrc[s] + g_adst[d];
    v = (v > 0.f) ? v : 0.2f * v;          // ATT_SLOPE
    g_edge_e[e] = v;
    atomicMaxFloat(&g_emax[d], v);
}

// ---------------- edge pass B: p, denom, weighted message (warp per edge) --
__global__ void k_edgeB(const int* __restrict__ src,
                        const int* __restrict__ dst) {
    int gw = (blockIdx.x * blockDim.x + threadIdx.x) >> 5;
    int lane = threadIdx.x & 31;
    if (gw >= EE) return;
    int s = src[gw], d = dst[gw];                    // broadcast loads
    float p = expf(g_edge_e[gw] - g_emax[d]);
    if (lane == 0) atomicAdd(&g_denom[d], p);
    const float* hs = g_h + (size_t)s * DD;
    float* md = g_msg + (size_t)d * DD;
#pragma unroll
    for (int j = 0; j < 4; j++) {
        int c = lane + 32 * j;
        atomicAdd(&md[c], p * hs[c]);
    }
}

// ---------------- finalize + BN column stats (layers 0,1) ------------------
__global__ __launch_bounds__(256) void k_finalize_bn(const float* __restrict__ bias) {
    __shared__ float ssum[DD], ssq[DD];
    int t = threadIdx.x;                   // 256
    int c = t & 127, half = t >> 7;
    if (t < DD) { ssum[t] = 0.f; ssq[t] = 0.f; }
    __syncthreads();
    int r0 = blockIdx.x * 128;
    int rend = r0 + 128; if (rend > NN) rend = NN;
    float ls = 0.f, lq = 0.f;
    for (int r = r0 + half; r < rend; r += 2) {
        size_t idx = (size_t)r * DD + c;
        float v = g_msg[idx] / (g_denom[r] + 1e-16f) + bias[c];
        g_out[idx] = v;
        ls += v; lq += v * v;
    }
    atomicAdd(&ssum[c], ls); atomicAdd(&ssq[c], lq);
    __syncthreads();
    if (t < DD) { atomicAdd(&g_colsum[t], ssum[t]); atomicAdd(&g_colsq[t], ssq[t]); }
}

// ---------------- finalize last layer: write directly to output ------------
__global__ void k_finalize_last(const float* __restrict__ bias,
                                float* __restrict__ dout) {
    int idx = blockIdx.x * blockDim.x + threadIdx.x;
    if (idx >= ND) return;
    int r = idx >> 7, c = idx & 127;
    dout[idx] = g_msg[idx] / (g_denom[r] + 1e-16f) + bias[c];
}

// ---------------- BN stats -> mu, invstd -----------------------------------
__global__ void k_bnstats() {
    int t = threadIdx.x;
    if (t < DD) {
        float mu = g_colsum[t] / (float)NN;
        float var = g_colsq[t] / (float)NN - mu * mu;
        g_mu[t] = mu;
        g_istd[t] = rsqrtf(var + 1e-5f);
    }
}

// ---------------- apply BN + leaky + residual ------------------------------
__global__ void k_apply(int k, const float* __restrict__ gamma,
                        const float* __restrict__ beta) {
    int idx = blockIdx.x * blockDim.x + threadIdx.x;
    if (idx >= ND) return;
    int c = idx & 127;
    float v = gamma[c] * (g_out[idx] - g_mu[c]) * g_istd[c] + beta[c];
    v = (v > 0.f) ? v : 0.01f * v;         // ACT_SLOPE
    g_emb[k][idx] += v;
}

// ---------------- relation vector update: relv = relv @ W^T + b ------------
__global__ void k_rel(int k, const float* __restrict__ W,
                      const float* __restrict__ b, float* dout) {
    __shared__ float old[DD];
    int t = threadIdx.x;
    float* rv = g_relv + k * DD;
    old[t] = rv[t];
    __syncthreads();
    float acc = b[t];
#pragma unroll 8
    for (int j = 0; j < DD; j++) acc += old[j] * W[(size_t)t * DD + j];
    rv[t] = acc;
    if (dout) dout[t] = acc;
}

// ===========================================================================
extern "C" void kernel_launch(void* const* d_in, const int* in_sizes, int n_in,
                              void* d_out, int out_size) {
    const float* features = (const float*)d_in[0];
    const float* rel_emb  = (const float*)d_in[1];
    const int*   edge     = (const int*)d_in[2];     // JAX default: int32
    const float* gat_W    = (const float*)d_in[3];
    const float* gat_asrc = (const float*)d_in[4];
    const float* gat_adst = (const float*)d_in[5];
    const float* gat_b    = (const float*)d_in[6];
    const float* bn_gamma = (const float*)d_in[7];
    const float* bn_beta  = (const float*)d_in[8];
    const float* rel_W    = (const float*)d_in[9];
    const float* rel_b    = (const float*)d_in[10];
    float* out = (float*)d_out;

    const int TB = 256;
    k_init<<<(ND + TB - 1) / TB, TB>>>(features, rel_emb);

    for (int i = 0; i < 3; i++) {
        for (int k = 0; k < RR; k++) {
            const int* src = edge + (size_t)k * 2 * EE;
            const int* dst = src + EE;

            k_reset<<<(ND + TB - 1) / TB, TB>>>();
            k_gemm<<<(NN + 63) / 64, 256>>>(k, gat_W + (size_t)i * DD * DD);
            k_alpha<<<(NN * 32 + TB - 1) / TB, TB>>>(gat_asrc + i * DD, gat_adst + i * DD);
            k_edgeA<<<(EE + TB - 1) / TB, TB>>>(src, dst);
            k_edgeB<<<(EE * 32 + TB - 1) / TB, TB>>>(src, dst);

            if (i < 2) {
                k_finalize_bn<<<(NN + 127) / 128, 256>>>(gat_b + i * DD);
                k_bnstats<<<1, DD>>>();
                k_apply<<<(ND + TB - 1) / TB, TB>>>(k, bn_gamma + i * DD, bn_beta + i * DD);
            } else {
                k_finalize_last<<<(ND + TB - 1) / TB, TB>>>(gat_b + i * DD,
                                                            out + (size_t)k * ND);
            }
            k_rel<<<1, DD>>>(k, rel_W + (size_t)i * DD * DD, rel_b + i * DD,
                             (i == 2) ? out + (size_t)4 * ND + k * DD : nullptr);
        }
    }
}

// round 6
// speedup vs baseline: 1.6765x; 1.6765x over previous
#include <cuda_runtime.h>

#define NN 50000
#define EE 800000
#define DD 128
#define RR 4
#define ND (NN*DD)

// ---------------- persistent scratch (device globals; no allocation) -------
__device__ float g_emb[RR][ND];          // per-relation node embeddings
__device__ float g_h[ND];                // GAT-transformed features
__device__ float g_out[ND];              // conv output (pre-BN)
__device__ float g_relv[RR*DD];          // relation vectors
__device__ float g_asrc[NN], g_adst[NN];
__device__ float g_colsum[DD], g_colsq[DD], g_mu[DD], g_istd[DD];
// CSR (built once per launch; graph static across layers)
__device__ int g_cnt[RR][NN];
__device__ int g_rowptr[RR][NN + 1];
__device__ int g_cursor[RR][NN];
__device__ int g_srcp[RR][EE];

// ---------------- init: emb[k] = features, relv = rel_emb ------------------
__global__ void k_init(const float* __restrict__ features,
                       const float* __restrict__ rel_emb) {
    int i = blockIdx.x * blockDim.x + threadIdx.x;
    if (i < ND) {
        float f = features[i];
#pragma unroll
        for (int k = 0; k < RR; k++) g_emb[k][i] = f;
    }
    if (i < RR * DD) g_relv[i] = rel_emb[i];
    if (i < RR * NN) ((int*)g_cnt)[i] = 0;
}

// ---------------- CSR build ------------------------------------------------
__global__ void k_hist(const int* __restrict__ edge) {
    int idx = blockIdx.x * blockDim.x + threadIdx.x;
    if (idx >= RR * EE) return;
    int k = idx / EE, e = idx - k * EE;
    int d = edge[(size_t)k * 2 * EE + EE + e];
    atomicAdd(&g_cnt[k][d], 1);
}

__global__ void k_scan() {                 // one block per relation
    __shared__ int sh[1024];
    int k = blockIdx.x;
    int t = threadIdx.x;
    const int CH = (NN + 1023) / 1024;     // 49
    int base = t * CH;
    int s = 0;
    for (int i = 0; i < CH; i++) { int idx = base + i; if (idx < NN) s += g_cnt[k][idx]; }
    sh[t] = s;
    __syncthreads();
    for (int o = 1; o < 1024; o <<= 1) {
        int v = (t >= o) ? sh[t - o] : 0;
        __syncthreads();
        sh[t] += v;
        __syncthreads();
    }
    int run = (t == 0) ? 0 : sh[t - 1];
    for (int i = 0; i < CH; i++) {
        int idx = base + i;
        if (idx < NN) {
            g_rowptr[k][idx] = run;
            g_cursor[k][idx] = run;
            run += g_cnt[k][idx];
        }
    }
    if (t == 1023) g_rowptr[k][NN] = run;  // == EE
}

__global__ void k_scatter(const int* __restrict__ edge) {
    int idx = blockIdx.x * blockDim.x + threadIdx.x;
    if (idx >= RR * EE) return;
    int k = idx / EE, e = idx - k * EE;
    int s = edge[(size_t)k * 2 * EE + e];
    int d = edge[(size_t)k * 2 * EE + EE + e];
    int pos = atomicAdd(&g_cursor[k][d], 1);
    g_srcp[k][pos] = s;
}

// ---------------- SGEMM: h = (emb[k]*relv[k]) @ W, fused alpha epilogue ----
// BM=64, BN=128(full), BK=32. 256 threads; thread tile 8 rows x 4 cols.
__global__ __launch_bounds__(256) void k_gemm(int k, const float* __restrict__ W,
                                              const float* __restrict__ a_src,
                                              const float* __restrict__ a_dst) {
    __shared__ float  xs[64][32];
    __shared__ float4 ws[32][32];
    const float* __restrict__ X  = g_emb[k];
    const float* __restrict__ rv = g_relv + k * DD;

    int tid = threadIdx.x;
    int tx = tid & 31, ty = tid >> 5;
    int row0 = blockIdx.x * 64;

    if (blockIdx.x == 0 && tid < DD) { g_colsum[tid] = 0.f; g_colsq[tid] = 0.f; }

    float acc[8][4];
#pragma unroll
    for (int i = 0; i < 8; i++)
#pragma unroll
        for (int j = 0; j < 4; j++) acc[i][j] = 0.f;

    for (int k0 = 0; k0 < DD; k0 += 32) {
#pragma unroll
        for (int j = 0; j < 8; j++) {
            int idx = tid + j * 256;
            int r = idx >> 5, kk = idx & 31;
            int gr = row0 + r;
            xs[r][kk] = (gr < NN) ? X[(size_t)gr * DD + k0 + kk] * rv[k0 + kk] : 0.f;
        }
#pragma unroll
        for (int j = 0; j < 4; j++) {
            int idx = tid + j * 256;
            int kk = idx >> 5, c4 = idx & 31;
            ws[kk][c4] = reinterpret_cast<const float4*>(W + (size_t)(k0 + kk) * DD)[c4];
        }
        __syncthreads();
#pragma unroll
        for (int kk = 0; kk < 32; kk++) {
            float4 b4 = ws[kk][tx];
#pragma unroll
            for (int i = 0; i < 8; i++) {
                float a = xs[ty * 8 + i][kk];
                acc[i][0] += a * b4.x; acc[i][1] += a * b4.y;
                acc[i][2] += a * b4.z; acc[i][3] += a * b4.w;
            }
        }
        __syncthreads();
    }

    float4 as4 = reinterpret_cast<const float4*>(a_src)[tx];
    float4 ad4 = reinterpret_cast<const float4*>(a_dst)[tx];
#pragma unroll
    for (int i = 0; i < 8; i++) {
        int gr = row0 + ty * 8 + i;
        if (gr < NN) {
            float4 v = make_float4(acc[i][0], acc[i][1], acc[i][2], acc[i][3]);
            reinterpret_cast<float4*>(g_h + (size_t)gr * DD)[tx] = v;
        }
        float s1 = acc[i][0] * as4.x + acc[i][1] * as4.y + acc[i][2] * as4.z + acc[i][3] * as4.w;
        float s2 = acc[i][0] * ad4.x + acc[i][1] * ad4.y + acc[i][2] * ad4.z + acc[i][3] * ad4.w;
#pragma unroll
        for (int o = 16; o; o >>= 1) {
            s1 += __shfl_xor_sync(0xffffffffu, s1, o);
            s2 += __shfl_xor_sync(0xffffffffu, s2, o);
        }
        if (tx == 0 && gr < NN) { g_asrc[gr] = s1; g_adst[gr] = s2; }
    }
}

// ---------------- aggregation: warp per dst node (gather, no atomics) ------
// fused: attention softmax + weighted sum + /denom + bias (+ BN stats).
// outp == nullptr -> write internal g_out scratch.
__global__ __launch_bounds__(256) void k_agg(int k, const float* __restrict__ bias,
                                             float* __restrict__ outp, int do_stats) {
    __shared__ float ssum[DD], ssq[DD];
    int t = threadIdx.x;
    if (do_stats) {
        if (t < DD) { ssum[t] = 0.f; ssq[t] = 0.f; }
        __syncthreads();
    }
    float* __restrict__ op = outp ? outp : g_out;
    int node = (blockIdx.x * 256 + t) >> 5;
    int lane = t & 31;
    float4 res = make_float4(0.f, 0.f, 0.f, 0.f);
    bool valid = (node < NN);
    if (valid) {
        int b0 = g_rowptr[k][node], b1 = g_rowptr[k][node + 1];
        float adst_d = g_adst[node];
        const int* __restrict__ sp = g_srcp[k];
        float mx = -3.402823e38f;
        for (int j = b0 + lane; j < b1; j += 32) {
            float e = g_asrc[sp[j]] + adst_d;
            e = (e > 0.f) ? e : 0.2f * e;
            mx = fmaxf(mx, e);
        }
#pragma unroll
        for (int o = 16; o; o >>= 1) mx = fmaxf(mx, __shfl_xor_sync(0xffffffffu, mx, o));

        float4 acc = make_float4(0.f, 0.f, 0.f, 0.f);
        float den = 0.f;
        for (int j = b0; j < b1; j++) {
            int s = sp[j];
            float e = g_asrc[s] + adst_d;
            e = (e > 0.f) ? e : 0.2f * e;
            float p = expf(e - mx);
            den += p;
            float4 hv = reinterpret_cast<const float4*>(g_h + (size_t)s * DD)[lane];
            acc.x += p * hv.x; acc.y += p * hv.y; acc.z += p * hv.z; acc.w += p * hv.w;
        }
        float inv = 1.f / (den + 1e-16f);
        float4 b4 = reinterpret_cast<const float4*>(bias)[lane];
        res.x = acc.x * inv + b4.x;
        res.y = acc.y * inv + b4.y;
        res.z = acc.z * inv + b4.z;
        res.w = acc.w * inv + b4.w;
        reinterpret_cast<float4*>(op + (size_t)node * DD)[lane] = res;
    }
    if (do_stats) {
        if (valid) {
            int c = lane * 4;
            atomicAdd(&ssum[c + 0], res.x); atomicAdd(&ssq[c + 0], res.x * res.x);
            atomicAdd(&ssum[c + 1], res.y); atomicAdd(&ssq[c + 1], res.y * res.y);
            atomicAdd(&ssum[c + 2], res.z); atomicAdd(&ssq[c + 2], res.z * res.z);
            atomicAdd(&ssum[c + 3], res.w); atomicAdd(&ssq[c + 3], res.w * res.w);
        }
        __syncthreads();
        if (t < DD) { atomicAdd(&g_colsum[t], ssum[t]); atomicAdd(&g_colsq[t], ssq[t]); }
    }
}

// ---------------- BN stats -> mu, invstd -----------------------------------
__global__ void k_bnstats() {
    int t = threadIdx.x;
    if (t < DD) {
        float mu = g_colsum[t] / (float)NN;
        float var = g_colsq[t] / (float)NN - mu * mu;
        g_mu[t] = mu;
        g_istd[t] = rsqrtf(var + 1e-5f);
    }
}

// ---------------- apply BN + leaky + residual ------------------------------
__global__ void k_apply(int k, const float* __restrict__ gamma,
                        const float* __restrict__ beta) {
    int idx = blockIdx.x * blockDim.x + threadIdx.x;
    if (idx >= ND) return;
    int c = idx & 127;
    float v = gamma[c] * (g_out[idx] - g_mu[c]) * g_istd[c] + beta[c];
    v = (v > 0.f) ? v : 0.01f * v;         // ACT_SLOPE
    g_emb[k][idx] += v;
}

// ---------------- relation vector update: relv = relv @ W^T + b ------------
__global__ void k_rel(int k, const float* __restrict__ W,
                      const float* __restrict__ b, float* dout) {
    __shared__ float old[DD];
    int t = threadIdx.x;
    float* rv = g_relv + k * DD;
    old[t] = rv[t];
    __syncthreads();
    float acc = b[t];
#pragma unroll 8
    for (int j = 0; j < DD; j++) acc += old[j] * W[(size_t)t * DD + j];
    rv[t] = acc;
    if (dout) dout[t] = acc;
}

// ===========================================================================
extern "C" void kernel_launch(void* const* d_in, const int* in_sizes, int n_in,
                              void* d_out, int out_size) {
    const float* features = (const float*)d_in[0];
    const float* rel_emb  = (const float*)d_in[1];
    const int*   edge     = (const int*)d_in[2];     // JAX default: int32
    const float* gat_W    = (const float*)d_in[3];
    const float* gat_asrc = (const float*)d_in[4];
    const float* gat_adst = (const float*)d_in[5];
    const float* gat_b    = (const float*)d_in[6];
    const float* bn_gamma = (const float*)d_in[7];
    const float* bn_beta  = (const float*)d_in[8];
    const float* rel_W    = (const float*)d_in[9];
    const float* rel_b    = (const float*)d_in[10];
    float* out = (float*)d_out;

    const int TB = 256;
    k_init<<<(ND + TB - 1) / TB, TB>>>(features, rel_emb);
    k_hist<<<(RR * EE + TB - 1) / TB, TB>>>(edge);
    k_scan<<<RR, 1024>>>();
    k_scatter<<<(RR * EE + TB - 1) / TB, TB>>>(edge);

    for (int i = 0; i < 3; i++) {
        for (int k = 0; k < RR; k++) {
            k_gemm<<<(NN + 63) / 64, 256>>>(k, gat_W + (size_t)i * DD * DD,
                                            gat_asrc + i * DD, gat_adst + i * DD);
            if (i < 2) {
                k_agg<<<(NN * 32 + 255) / 256, 256>>>(k, gat_b + i * DD, nullptr, 1);
                k_bnstats<<<1, DD>>>();
                k_apply<<<(ND + TB - 1) / TB, TB>>>(k, bn_gamma + i * DD, bn_beta + i * DD);
            } else {
                k_agg<<<(NN * 32 + 255) / 256, 256>>>(k, gat_b + i * DD,
                                                      out + (size_t)k * ND, 0);
            }
            k_rel<<<1, DD>>>(k, rel_W + (size_t)i * DD * DD, rel_b + i * DD,
                             (i == 2) ? out + (size_t)4 * ND + k * DD : nullptr);
        }
    }
}

// round 9
// speedup vs baseline: 1.8315x; 1.0924x over previous
#include <cuda_runtime.h>

#define NN 50000
#define EE 800000
#define DD 128
#define RR 4
#define ND (NN*DD)

// ---------------- persistent scratch (device globals; no allocation) -------
__device__ float g_emb[RR][ND];          // per-relation node embeddings
__device__ float g_h[ND];                // GAT-transformed features
__device__ float g_out[ND];              // conv output (pre-BN)
__device__ float g_relv[RR*DD];          // relation vectors
__device__ float g_asrc[NN], g_adst[NN];
__device__ float g_colsum[DD], g_colsq[DD], g_mu[DD], g_istd[DD];
__device__ unsigned g_done;              // zero-initialized; reset after each use
// CSR (built once per launch; graph static across layers)
__device__ int g_cnt[RR][NN];
__device__ int g_rowptr[RR][NN + 1];
__device__ int g_cursor[RR][NN];
__device__ int g_srcp[RR][EE];

// ---------------- packed f32x2 helpers (Blackwell FFMA2) -------------------
__device__ __forceinline__ void ffma2(unsigned long long& d,
                                      unsigned long long a, unsigned long long b) {
    asm("fma.rn.f32x2 %0, %1, %2, %0;" : "+l"(d) : "l"(a), "l"(b));
}
__device__ __forceinline__ unsigned long long pack2(float x) {
    unsigned long long r;
    asm("mov.b64 %0, {%1, %1};" : "=l"(r) : "f"(x));
    return r;
}
__device__ __forceinline__ void unpack2(unsigned long long d, float& lo, float& hi) {
    asm("mov.b64 {%0, %1}, %2;" : "=f"(lo), "=f"(hi) : "l"(d));
}

// ---------------- init: emb[k] = features, relv = rel_emb ------------------
__global__ void k_init(const float* __restrict__ features,
                       const float* __restrict__ rel_emb) {
    int i = blockIdx.x * blockDim.x + threadIdx.x;
    if (i < ND) {
        float f = features[i];
#pragma unroll
        for (int k = 0; k < RR; k++) g_emb[k][i] = f;
    }
    if (i < RR * DD) g_relv[i] = rel_emb[i];
    if (i < RR * NN) ((int*)g_cnt)[i] = 0;
}

// ---------------- CSR build ------------------------------------------------
__global__ void k_hist(const int* __restrict__ edge) {
    int idx = blockIdx.x * blockDim.x + threadIdx.x;
    if (idx >= RR * EE) return;
    int k = idx / EE, e = idx - k * EE;
    int d = edge[(size_t)k * 2 * EE + EE + e];
    atomicAdd(&g_cnt[k][d], 1);
}

__global__ void k_scan() {                 // one block per relation
    __shared__ int sh[1024];
    int k = blockIdx.x;
    int t = threadIdx.x;
    const int CH = (NN + 1023) / 1024;     // 49
    int base = t * CH;
    int s = 0;
    for (int i = 0; i < CH; i++) { int idx = base + i; if (idx < NN) s += g_cnt[k][idx]; }
    sh[t] = s;
    __syncthreads();
    for (int o = 1; o < 1024; o <<= 1) {
        int v = (t >= o) ? sh[t - o] : 0;
        __syncthreads();
        sh[t] += v;
        __syncthreads();
    }
    int run = (t == 0) ? 0 : sh[t - 1];
    for (int i = 0; i < CH; i++) {
        int idx = base + i;
        if (idx < NN) {
            g_rowptr[k][idx] = run;
            g_cursor[k][idx] = run;
            run += g_cnt[k][idx];
        }
    }
    if (t == 1023) g_rowptr[k][NN] = run;  // == EE
}

__global__ void k_scatter(const int* __restrict__ edge) {
    int idx = blockIdx.x * blockDim.x + threadIdx.x;
    if (idx >= RR * EE) return;
    int k = idx / EE, e = idx - k * EE;
    int s = edge[(size_t)k * 2 * EE + e];
    int d = edge[(size_t)k * 2 * EE + EE + e];
    int pos = atomicAdd(&g_cursor[k][d], 1);
    g_srcp[k][pos] = s;
}

// ---------------- SGEMM (packed FFMA2): h = (emb[k]*relv[k]) @ W -----------
// BM=64, BN=128, BK=32. 256 threads; thread tile 8 rows x 4 cols.
// Rows paired into f32x2 lanes; x-tile stored kk-major so a-pairs come from LDS.64.
__global__ __launch_bounds__(256) void k_gemm(int k, const float* __restrict__ W,
                                              const float* __restrict__ a_src,
                                              const float* __restrict__ a_dst) {
    __shared__ float  xs[32][66];      // [kk][row], pad 66 keeps LDS.64 aligned, 2-way max
    __shared__ float4 ws[32][32];      // ws[kk][c4]
    const float* __restrict__ X  = g_emb[k];
    const float* __restrict__ rv = g_relv + k * DD;

    int tid = threadIdx.x;
    int tx = tid & 31, ty = tid >> 5;
    int row0 = blockIdx.x * 64;

    if (blockIdx.x == 0 && tid < DD) { g_colsum[tid] = 0.f; g_colsq[tid] = 0.f; }

    unsigned long long accp[4][4];     // [rowpair][col]: packs rows (2p, 2p+1)
#pragma unroll
    for (int p = 0; p < 4; p++)
#pragma unroll
        for (int c = 0; c < 4; c++) accp[p][c] = 0ull;

    for (int k0 = 0; k0 < DD; k0 += 32) {
#pragma unroll
        for (int j = 0; j < 8; j++) {
            int idx = tid + j * 256;
            int r = idx >> 5, kk = idx & 31;
            int gr = row0 + r;
            xs[kk][r] = (gr < NN) ? X[(size_t)gr * DD + k0 + kk] * rv[k0 + kk] : 0.f;
        }
#pragma unroll
        for (int j = 0; j < 4; j++) {
            int idx = tid + j * 256;
            int kk = idx >> 5, c4 = idx & 31;
            ws[kk][c4] = reinterpret_cast<const float4*>(W + (size_t)(k0 + kk) * DD)[c4];
        }
        __syncthreads();
#pragma unroll
        for (int kk = 0; kk < 32; kk++) {
            float4 b4 = ws[kk][tx];
            unsigned long long bx = pack2(b4.x), by = pack2(b4.y),
                               bz = pack2(b4.z), bw = pack2(b4.w);
            const unsigned long long* ap =
                reinterpret_cast<const unsigned long long*>(&xs[kk][ty * 8]);
#pragma unroll
            for (int p = 0; p < 4; p++) {
                unsigned long long a2 = ap[p];
                ffma2(accp[p][0], a2, bx);
                ffma2(accp[p][1], a2, by);
                ffma2(accp[p][2], a2, bz);
                ffma2(accp[p][3], a2, bw);
            }
        }
        __syncthreads();
    }

    float4 as4 = reinterpret_cast<const float4*>(a_src)[tx];
    float4 ad4 = reinterpret_cast<const float4*>(a_dst)[tx];
#pragma unroll
    for (int p = 0; p < 4; p++) {
        float lo[4], hi[4];
#pragma unroll
        for (int c = 0; c < 4; c++) unpack2(accp[p][c], lo[c], hi[c]);
#pragma unroll
        for (int half = 0; half < 2; half++) {
            float v0 = half ? hi[0] : lo[0];
            float v1 = half ? hi[1] : lo[1];
            float v2 = half ? hi[2] : lo[2];
            float v3 = half ? hi[3] : lo[3];
            int gr = row0 + ty * 8 + 2 * p + half;
            if (gr < NN)
                reinterpret_cast<float4*>(g_h + (size_t)gr * DD)[tx] =
                    make_float4(v0, v1, v2, v3);
            float s1 = v0 * as4.x + v1 * as4.y + v2 * as4.z + v3 * as4.w;
            float s2 = v0 * ad4.x + v1 * ad4.y + v2 * ad4.z + v3 * ad4.w;
#pragma unroll
            for (int o = 16; o; o >>= 1) {
                s1 += __shfl_xor_sync(0xffffffffu, s1, o);
                s2 += __shfl_xor_sync(0xffffffffu, s2, o);
            }
            if (tx == 0 && gr < NN) { g_asrc[gr] = s1; g_adst[gr] = s2; }
        }
    }
}

// ---------------- aggregation: warp per dst node (gather, no atomics) ------
// fused: softmax + weighted sum + /denom + bias (+ BN stats + mu/istd in last block)
__global__ __launch_bounds__(256) void k_agg(int k, const float* __restrict__ bias,
                                             float* __restrict__ outp, int do_stats) {
    __shared__ float ssum[DD], ssq[DD];
    __shared__ unsigned s_rank;
    int t = threadIdx.x;
    if (do_stats) {
        if (t < DD) { ssum[t] = 0.f; ssq[t] = 0.f; }
        __syncthreads();
    }
    float* __restrict__ op = outp ? outp : g_out;
    int node = (blockIdx.x * 256 + t) >> 5;
    int lane = t & 31;
    float4 res = make_float4(0.f, 0.f, 0.f, 0.f);
    bool valid = (node < NN);
    if (valid) {
        int b0 = g_rowptr[k][node], b1 = g_rowptr[k][node + 1];
        float adst_d = g_adst[node];
        const int* __restrict__ sp = g_srcp[k];

        // pass 1: per-lane e for first 64 edges cached in regs; warp max
        float e0 = -3.402823e38f, e1 = -3.402823e38f;
        int ja = b0 + lane, jb = b0 + lane + 32;
        if (ja < b1) { float e = g_asrc[sp[ja]] + adst_d; e0 = (e > 0.f) ? e : 0.2f * e; }
        if (jb < b1) { float e = g_asrc[sp[jb]] + adst_d; e1 = (e > 0.f) ? e : 0.2f * e; }
        float mx = fmaxf(e0, e1);
        for (int j = b0 + lane + 64; j < b1; j += 32) {
            float e = g_asrc[sp[j]] + adst_d;
            e = (e > 0.f) ? e : 0.2f * e;
            mx = fmaxf(mx, e);
        }
#pragma unroll
        for (int o = 16; o; o >>= 1) mx = fmaxf(mx, __shfl_xor_sync(0xffffffffu, mx, o));

        // e lookup: shuffle-broadcast from cached regs (i uniform across warp)
        auto getE = [&](int i) -> float {
            if (i < 32) return __shfl_sync(0xffffffffu, e0, i);
            if (i < 64) return __shfl_sync(0xffffffffu, e1, i - 32);
            float e = g_asrc[sp[b0 + i]] + adst_d;
            return (e > 0.f) ? e : 0.2f * e;
        };

        // pass 2: 4x-unrolled gathers (MLP=4), register accumulation
        float4 acc = make_float4(0.f, 0.f, 0.f, 0.f);
        float den = 0.f;
        const float4* __restrict__ H = reinterpret_cast<const float4*>(g_h);
        int j = b0;
        for (; j + 4 <= b1; j += 4) {
            int i0 = j - b0;
            int s0 = sp[j], s1 = sp[j + 1], s2 = sp[j + 2], s3 = sp[j + 3];
            float4 h0 = H[(size_t)s0 * 32 + lane];
            float4 h1 = H[(size_t)s1 * 32 + lane];
            float4 h2 = H[(size_t)s2 * 32 + lane];
            float4 h3 = H[(size_t)s3 * 32 + lane];
            float p0 = expf(getE(i0 + 0) - mx);
            float p1 = expf(getE(i0 + 1) - mx);
            float p2 = expf(getE(i0 + 2) - mx);
            float p3 = expf(getE(i0 + 3) - mx);
            den   += (p0 + p1) + (p2 + p3);
            acc.x += p0 * h0.x + p1 * h1.x + p2 * h2.x + p3 * h3.x;
            acc.y += p0 * h0.y + p1 * h1.y + p2 * h2.y + p3 * h3.y;
            acc.z += p0 * h0.z + p1 * h1.z + p2 * h2.z + p3 * h3.z;
            acc.w += p0 * h0.w + p1 * h1.w + p2 * h2.w + p3 * h3.w;
        }
        for (; j < b1; j++) {
            int s = sp[j];
            float4 hv = H[(size_t)s * 32 + lane];
            float p = expf(getE(j - b0) - mx);
            den += p;
            acc.x += p * hv.x; acc.y += p * hv.y; acc.z += p * hv.z; acc.w += p * hv.w;
        }
        float inv = 1.f / (den + 1e-16f);
        float4 b4 = reinterpret_cast<const float4*>(bias)[lane];
        res.x = acc.x * inv + b4.x;
        res.y = acc.y * inv + b4.y;
        res.z = acc.z * inv + b4.z;
        res.w = acc.w * inv + b4.w;
        reinterpret_cast<float4*>(op + (size_t)node * DD)[lane] = res;
    }
    if (do_stats) {
        if (valid) {
            int c = lane * 4;
            atomicAdd(&ssum[c + 0], res.x); atomicAdd(&ssq[c + 0], res.x * res.x);
            atomicAdd(&ssum[c + 1], res.y); atomicAdd(&ssq[c + 1], res.y * res.y);
            atomicAdd(&ssum[c + 2], res.z); atomicAdd(&ssq[c + 2], res.z * res.z);
            atomicAdd(&ssum[c + 3], res.w); atomicAdd(&ssq[c + 3], res.w * res.w);
        }
        __syncthreads();
        if (t < DD) { atomicAdd(&g_colsum[t], ssum[t]); atomicAdd(&g_colsq[t], ssq[t]); }
        __threadfence();
        __syncthreads();
        if (t == 0) s_rank = atomicAdd(&g_done, 1u);
        __syncthreads();
        if (s_rank == gridDim.x - 1) {           // last block: finalize BN stats
            __threadfence();
            if (t < DD) {
                float cs = atomicAdd(&g_colsum[t], 0.f);   // L2-coherent read
                float cq = atomicAdd(&g_colsq[t], 0.f);
                float mu = cs / (float)NN;
                float var = cq / (float)NN - mu * mu;
                g_mu[t] = mu;
                g_istd[t] = rsqrtf(var + 1e-5f);
            }
            if (t == 0) g_done = 0u;
        }
    }
}

// ---------------- apply BN + leaky + residual ------------------------------
__global__ void k_apply(int k, const float* __restrict__ gamma,
                        const float* __restrict__ beta) {
    int idx = blockIdx.x * blockDim.x + threadIdx.x;
    if (idx >= ND) return;
    int c = idx & 127;
    float v = gamma[c] * (g_out[idx] - g_mu[c]) * g_istd[c] + beta[c];
    v = (v > 0.f) ? v : 0.01f * v;         // ACT_SLOPE
    g_emb[k][idx] += v;
}

// ---------------- relation vector update: relv = relv @ W^T + b ------------
// 1024 threads: warp per output row (4 rows each), coalesced W reads.
__global__ __launch_bounds__(1024) void k_rel(int k, const float* __restrict__ W,
                                              const float* __restrict__ b, float* dout) {
    __shared__ float old[DD];
    int t = threadIdx.x;
    int warp = t >> 5, lane = t & 31;
    if (t < DD) old[t] = g_relv[k * DD + t];
    __syncthreads();
    for (int o = warp; o < DD; o += 32) {
        float s = 0.f;
#pragma unroll
        for (int q = 0; q < 4; q++)
            s += old[lane + 32 * q] * W[(size_t)o * DD + lane + 32 * q];
#pragma unroll
        for (int of = 16; of; of >>= 1) s += __shfl_xor_sync(0xffffffffu, s, of);
        if (lane == 0) {
            float r = s + b[o];
            g_relv[k * DD + o] = r;
            if (dout) dout[o] = r;
        }
    }
}

// ===========================================================================
extern "C" void kernel_launch(void* const* d_in, const int* in_sizes, int n_in,
                              void* d_out, int out_size) {
    const float* features = (const float*)d_in[0];
    const float* rel_emb  = (const float*)d_in[1];
    const int*   edge     = (const int*)d_in[2];     // JAX default: int32
    const float* gat_W    = (const float*)d_in[3];
    const float* gat_asrc = (const float*)d_in[4];
    const float* gat_adst = (const float*)d_in[5];
    const float* gat_b    = (const float*)d_in[6];
    const float* bn_gamma = (const float*)d_in[7];
    const float* bn_beta  = (const float*)d_in[8];
    const float* rel_W    = (const float*)d_in[9];
    const float* rel_b    = (const float*)d_in[10];
    float* out = (float*)d_out;

    const int TB = 256;
    k_init<<<(ND + TB - 1) / TB, TB>>>(features, rel_emb);
    k_hist<<<(RR * EE + TB - 1) / TB, TB>>>(edge);
    k_scan<<<RR, 1024>>>();
    k_scatter<<<(RR * EE + TB - 1) / TB, TB>>>(edge);

    for (int i = 0; i < 3; i++) {
        for (int k = 0; k < RR; k++) {
            k_gemm<<<(NN + 63) / 64, 256>>>(k, gat_W + (size_t)i * DD * DD,
                                            gat_asrc + i * DD, gat_adst + i * DD);
            if (i < 2) {
                k_agg<<<(NN * 32 + 255) / 256, 256>>>(k, gat_b + i * DD, nullptr, 1);
                k_apply<<<(ND + TB - 1) / TB, TB>>>(k, bn_gamma + i * DD, bn_beta + i * DD);
            } else {
                k_agg<<<(NN * 32 + 255) / 256, 256>>>(k, gat_b + i * DD,
                                                      out + (size_t)k * ND, 0);
            }
            k_rel<<<1, 1024>>>(k, rel_W + (size_t)i * DD * DD, rel_b + i * DD,
                               (i == 2) ? out + (size_t)4 * ND + k * DD : nullptr);
        }
    }
}